// round 1
// baseline (speedup 1.0000x reference)
#include <cuda_runtime.h>

#define HID    64
#define BATCH  16384
#define NSTEPS 100
#define DT     0.01f

// scratch (no allocations allowed)
__device__ float g_scalars[3];   // p0, dp0, pi0
__device__ float g_pA[128];
__device__ float g_pB[128];

__device__ __forceinline__ float fast_tanh(float v) {
    // tanh(v) = sign(v) * (1 - e) / (1 + e),  e = exp(-2|v|)
    float av = fabsf(v);
    float e  = __expf(-2.0f * av);
    float r  = __fdividef(1.0f - e, 1.0f + e);
    return copysignf(r, v);
}

// ---------------------------------------------------------------------------
// Scalar prep: p0 = p_net([0, X0, R0]), dp0 = d p0 / d x, pi0 = q_net([0, X0, R0])
// One block of 64 threads (thread j owns hidden unit j).
// ---------------------------------------------------------------------------
__global__ void prep_kernel(
    const float* __restrict__ X0, const float* __restrict__ R0,
    const float* __restrict__ pW1, const float* __restrict__ pb1,
    const float* __restrict__ pW2, const float* __restrict__ pb2,
    const float* __restrict__ pW3, const float* __restrict__ pb3,
    const float* __restrict__ qW1, const float* __restrict__ qb1,
    const float* __restrict__ qW2, const float* __restrict__ qb2,
    const float* __restrict__ qW3, const float* __restrict__ qb3)
{
    __shared__ float h1[HID], d1[HID], tA[HID], tB[HID];
    int j = threadIdx.x;
    float x0 = X0[0], r0 = R0[0];

    // ---- p-net, state s = [0, x0, r0]; tangent ds/dx = e1 ----
    float a = pW1[HID + j] * x0 + pW1[2 * HID + j] * r0 + pb1[j];
    float h = fast_tanh(a);
    h1[j] = h;
    d1[j] = (1.0f - h * h) * pW1[HID + j];
    __syncthreads();

    float acc = pb2[j], dacc = 0.0f;
    for (int k = 0; k < HID; ++k) {
        float w = pW2[k * HID + j];
        acc  += h1[k] * w;
        dacc += d1[k] * w;
    }
    float h2 = fast_tanh(acc);
    float d2 = (1.0f - h2 * h2) * dacc;
    tA[j] = h2 * pW3[j];
    tB[j] = d2 * pW3[j];
    __syncthreads();
    if (j == 0) {
        float s = pb3[0], sd = 0.0f;
        for (int k = 0; k < HID; ++k) { s += tA[k]; sd += tB[k]; }
        g_scalars[0] = s;   // p0
        g_scalars[1] = sd;  // dp0
    }
    __syncthreads();

    // ---- q-net pi0, same state ----
    float aq = qW1[HID + j] * x0 + qW1[2 * HID + j] * r0 + qb1[j];
    float hq = fast_tanh(aq);
    __syncthreads();           // protect h1 reuse
    h1[j] = hq;
    __syncthreads();
    float accq = qb2[j];
    for (int k = 0; k < HID; ++k) accq += h1[k] * qW2[k * HID + j];
    tA[j] = fast_tanh(accq) * qW3[j];
    __syncthreads();
    if (j == 0) {
        float s = qb3[0];
        for (int k = 0; k < HID; ++k) s += tA[k];
        g_scalars[2] = s;   // pi0
    }
}

// ---------------------------------------------------------------------------
// Main persistent simulation: one thread per sample, all 100 steps in-kernel.
// q-net weights in shared memory; h1 in registers (fully unrolled indices).
// ---------------------------------------------------------------------------
__global__ void __launch_bounds__(128) sim_kernel(
    const float* __restrict__ dw,
    const float* __restrict__ X0, const float* __restrict__ R0,
    const float* __restrict__ qW1, const float* __restrict__ qb1,
    const float* __restrict__ qW2, const float* __restrict__ qb2,
    const float* __restrict__ qW3, const float* __restrict__ qb3,
    float* __restrict__ out)
{
    __shared__ __align__(16) float sW2[HID * HID];
    __shared__ float sW1[3 * HID], sb1[HID], sb2[HID], sW3[HID];
    __shared__ float sb3s;
    __shared__ float redA[128], redB[128];

    int tid = threadIdx.x;
    for (int i = tid; i < HID * HID; i += 128) sW2[i] = qW2[i];
    for (int i = tid; i < 3 * HID; i += 128)   sW1[i] = qW1[i];
    if (tid < HID) { sb1[tid] = qb1[tid]; sb2[tid] = qb2[tid]; sW3[tid] = qW3[tid]; }
    if (tid == 0)  sb3s = qb3[0];
    __syncthreads();

    const float p0  = g_scalars[0];
    const float dp0 = g_scalars[1];
    const float pi0 = g_scalars[2];
    const float x0v = X0[0], r0v = R0[0];

    int b = blockIdx.x * 128 + tid;
    const float* __restrict__ dwp = dw + b * NSTEPS;

    // model constants
    const float C_ADT  = 0.05f * 0.01f;            // alpha*dt
    const float C_STDT = 0.2f * 0.3f * 0.01f;      // sigma*theta*dt
    const float SIG    = 0.2f;
    const float BEFF   = 0.1f;                     // sign(rho)*B
    const float C_R1   = 0.02f - 0.5f * 0.1f * 0.1f;       // A - 0.5*b^2
    const float C_P1   = -(0.05f + 0.5f * 0.3f * 0.3f);    // -(alpha + 0.5*theta^2)
    const float TH     = 0.3f;

    // step-0 row
    {
        unsigned base = (unsigned)b * 5u;
        out[base + 0] = x0v; out[base + 1] = r0v; out[base + 2] = pi0;
        out[base + 3] = -p0; out[base + 4] = -dp0;
    }

    float x = x0v, mn = x0v, W = 0.0f, pi = pi0;
    float Rv = r0v, p = p0;

    for (int i = 1; i <= NSTEPS; ++i) {
        float dwi = dwp[i - 1];
        x = x + x * C_ADT + pi * C_STDT + pi * SIG * dwi;
        mn = fminf(mn, x);
        W += dwi;
        float t = (float)i * DT;
        Rv = r0v * __expf(C_R1 * t + BEFF * W);
        p  = p0  * __expf(C_P1 * t - TH * W);

        if (i < NSTEPS) {                 // pi not updated at last step
            float s0 = 2.0f * t;          // MULT * t
            float h1[HID];
            #pragma unroll
            for (int j = 0; j < HID; ++j)
                h1[j] = fast_tanh(sW1[j] * s0 + sW1[HID + j] * x
                                  + sW1[2 * HID + j] * Rv + sb1[j]);
            float o = sb3s;
            for (int j0 = 0; j0 < HID; j0 += 4) {
                float a0 = sb2[j0 + 0], a1 = sb2[j0 + 1];
                float a2 = sb2[j0 + 2], a3 = sb2[j0 + 3];
                const float4* wrow = (const float4*)(sW2 + j0);
                #pragma unroll
                for (int k = 0; k < HID; ++k) {
                    float4 w = wrow[k * (HID / 4)];
                    a0 += h1[k] * w.x; a1 += h1[k] * w.y;
                    a2 += h1[k] * w.z; a3 += h1[k] * w.w;
                }
                o += fast_tanh(a0) * sW3[j0 + 0] + fast_tanh(a1) * sW3[j0 + 1]
                   + fast_tanh(a2) * sW3[j0 + 2] + fast_tanh(a3) * sW3[j0 + 3];
            }
            pi = o;
        }
        unsigned base = ((unsigned)i * BATCH + (unsigned)b) * 5u;
        out[base + 0] = x;  out[base + 1] = Rv; out[base + 2] = pi;
        out[base + 3] = -p; out[base + 4] = -dp0;
    }

    // ---- per-sample loss terms ----
    float xc  = fmaxf(x, 1e-6f);
    float ux  = Rv * rsqrtf(xc);            // R * xc^(gamma-1), gamma=0.5
    float uv  = 2.0f * Rv * sqrtf(xc);      // R * xc^gamma / gamma
    float dpn = fmaxf(1e-6f - mn, 0.0f);
    float pen = 100.0f * dpn * dpn;
    float aa  = p + ux; aa = aa * aa + pen; // (p_fin + ux)^2 + pen
    float bb  = -uv + pen;                  // -u_val + pen

    redA[tid] = aa; redB[tid] = bb;
    __syncthreads();
    for (int s = 64; s > 0; s >>= 1) {
        if (tid < s) { redA[tid] += redA[tid + s]; redB[tid] += redB[tid + s]; }
        __syncthreads();
    }
    if (tid == 0) { g_pA[blockIdx.x] = redA[0]; g_pB[blockIdx.x] = redB[0]; }
}

// ---------------------------------------------------------------------------
// Deterministic final reduction of the 128 block partials -> two losses.
// ---------------------------------------------------------------------------
__global__ void finalize_kernel(float* __restrict__ out)
{
    __shared__ float rA[128], rB[128];
    int tid = threadIdx.x;
    rA[tid] = g_pA[tid]; rB[tid] = g_pB[tid];
    __syncthreads();
    for (int s = 64; s > 0; s >>= 1) {
        if (tid < s) { rA[tid] += rA[tid + s]; rB[tid] += rB[tid + s]; }
        __syncthreads();
    }
    if (tid == 0) {
        float lp  = rA[0] / (float)BATCH;
        float lpi = lp + rB[0] / (float)BATCH;
        unsigned base = (unsigned)(NSTEPS + 1) * BATCH * 5u;
        out[base + 0] = lp;
        out[base + 1] = lpi;
    }
}

extern "C" void kernel_launch(void* const* d_in, const int* in_sizes, int n_in,
                              void* d_out, int out_size)
{
    const float* dw  = (const float*)d_in[0];
    const float* X0  = (const float*)d_in[1];
    const float* R0  = (const float*)d_in[2];
    const float* pW1 = (const float*)d_in[3];  const float* pb1 = (const float*)d_in[4];
    const float* pW2 = (const float*)d_in[5];  const float* pb2 = (const float*)d_in[6];
    const float* pW3 = (const float*)d_in[7];  const float* pb3 = (const float*)d_in[8];
    const float* qW1 = (const float*)d_in[9];  const float* qb1 = (const float*)d_in[10];
    const float* qW2 = (const float*)d_in[11]; const float* qb2 = (const float*)d_in[12];
    const float* qW3 = (const float*)d_in[13]; const float* qb3 = (const float*)d_in[14];
    float* out = (float*)d_out;

    prep_kernel<<<1, 64>>>(X0, R0, pW1, pb1, pW2, pb2, pW3, pb3,
                           qW1, qb1, qW2, qb2, qW3, qb3);
    sim_kernel<<<128, 128>>>(dw, X0, R0, qW1, qb1, qW2, qb2, qW3, qb3, out);
    finalize_kernel<<<1, 128>>>(out);
}

// round 2
// speedup vs baseline: 1.0053x; 1.0053x over previous
#include <cuda_runtime.h>

#define HID    64
#define BATCH  16384
#define NSTEPS 100
#define DT     0.01f

// scratch (no allocations allowed)
__device__ float g_scalars[3];   // p0, dp0, pi0
__device__ float g_pA[128];
__device__ float g_pB[128];

typedef unsigned long long ull;

__device__ __forceinline__ float exact_tanh(float v) {
    float av = fabsf(v);
    float e  = __expf(-2.0f * av);
    float r  = __fdividef(1.0f - e, 1.0f + e);
    return copysignf(r, v);
}
__device__ __forceinline__ float tanh_ap(float x) {
    float y; asm("tanh.approx.f32 %0, %1;" : "=f"(y) : "f"(x)); return y;
}
__device__ __forceinline__ ull pack2(float lo, float hi) {
    ull r; asm("mov.b64 %0, {%1, %2};" : "=l"(r) : "f"(lo), "f"(hi)); return r;
}
__device__ __forceinline__ void unpack2(ull v, float& lo, float& hi) {
    asm("mov.b64 {%0, %1}, %2;" : "=f"(lo), "=f"(hi) : "l"(v));
}
__device__ __forceinline__ void ffma2(ull& d, ull a, ull b) {
    asm("fma.rn.f32x2 %0, %1, %2, %0;" : "+l"(d) : "l"(a), "l"(b));
}

// ---------------------------------------------------------------------------
// Scalar prep: p0 = p_net([0,X0,R0]), dp0 = d p0/dx, pi0 = q_net([0,X0,R0]).
// One block of 64 threads; exact tanh (scalars feed everything).
// ---------------------------------------------------------------------------
__global__ void prep_kernel(
    const float* __restrict__ X0, const float* __restrict__ R0,
    const float* __restrict__ pW1, const float* __restrict__ pb1,
    const float* __restrict__ pW2, const float* __restrict__ pb2,
    const float* __restrict__ pW3, const float* __restrict__ pb3,
    const float* __restrict__ qW1, const float* __restrict__ qb1,
    const float* __restrict__ qW2, const float* __restrict__ qb2,
    const float* __restrict__ qW3, const float* __restrict__ qb3)
{
    __shared__ float h1[HID], d1[HID], tA[HID], tB[HID];
    int j = threadIdx.x;
    float x0 = X0[0], r0 = R0[0];

    // ---- p-net, state s = [0, x0, r0]; tangent ds/dx = e1 ----
    float a = pW1[HID + j] * x0 + pW1[2 * HID + j] * r0 + pb1[j];
    float h = exact_tanh(a);
    h1[j] = h;
    d1[j] = (1.0f - h * h) * pW1[HID + j];
    __syncthreads();

    float acc = pb2[j], dacc = 0.0f;
    #pragma unroll 16
    for (int k = 0; k < HID; ++k) {
        float w = pW2[k * HID + j];
        acc  += h1[k] * w;
        dacc += d1[k] * w;
    }
    float h2 = exact_tanh(acc);
    float d2 = (1.0f - h2 * h2) * dacc;
    tA[j] = h2 * pW3[j];
    tB[j] = d2 * pW3[j];
    __syncthreads();
    if (j == 0) {
        float s = pb3[0], sd = 0.0f;
        for (int k = 0; k < HID; ++k) { s += tA[k]; sd += tB[k]; }
        g_scalars[0] = s;   // p0
        g_scalars[1] = sd;  // dp0
    }
    __syncthreads();

    // ---- q-net pi0 ----
    float aq = qW1[HID + j] * x0 + qW1[2 * HID + j] * r0 + qb1[j];
    float hq = exact_tanh(aq);
    __syncthreads();
    h1[j] = hq;
    __syncthreads();
    float accq = qb2[j];
    #pragma unroll 16
    for (int k = 0; k < HID; ++k) accq += h1[k] * qW2[k * HID + j];
    tA[j] = exact_tanh(accq) * qW3[j];
    __syncthreads();
    if (j == 0) {
        float s = qb3[0];
        for (int k = 0; k < HID; ++k) s += tA[k];
        g_scalars[2] = s;   // pi0
    }
}

// ---------------------------------------------------------------------------
// Main persistent simulation: one thread per sample, 100 steps in-kernel.
// GEMV uses packed f32x2 FMAs over output-unit pairs (32 packed accumulators),
// k-outer loop with just-in-time h1 tanh (hides MUFU under FFMA2 issue).
// ---------------------------------------------------------------------------
__global__ void __launch_bounds__(128) sim_kernel(
    const float* __restrict__ dw,
    const float* __restrict__ X0, const float* __restrict__ R0,
    const float* __restrict__ qW1, const float* __restrict__ qb1,
    const float* __restrict__ qW2, const float* __restrict__ qb2,
    const float* __restrict__ qW3, const float* __restrict__ qb3,
    float* __restrict__ out)
{
    __shared__ __align__(16) float sW2[HID * HID];
    __shared__ float sW1[3 * HID], sb1[HID], sW3[HID];
    __shared__ ull  sb2p[HID / 2];
    __shared__ float sb3s;
    __shared__ float redA[128], redB[128];

    int tid = threadIdx.x;
    for (int i = tid; i < HID * HID; i += 128) sW2[i] = qW2[i];
    for (int i = tid; i < 3 * HID; i += 128)   sW1[i] = qW1[i];
    if (tid < HID) { sb1[tid] = qb1[tid]; sW3[tid] = qW3[tid]; }
    if (tid < HID / 2) sb2p[tid] = pack2(qb2[2 * tid], qb2[2 * tid + 1]);
    if (tid == 0)  sb3s = qb3[0];
    __syncthreads();

    const float p0  = g_scalars[0];
    const float dp0 = g_scalars[1];
    const float pi0 = g_scalars[2];
    const float x0v = X0[0], r0v = R0[0];

    int b = blockIdx.x * 128 + tid;
    const float* __restrict__ dwp = dw + b * NSTEPS;

    const float C_ADT  = 0.05f * 0.01f;                    // alpha*dt
    const float C_STDT = 0.2f * 0.3f * 0.01f;              // sigma*theta*dt
    const float SIG    = 0.2f;
    const float BEFF   = 0.1f;                             // sign(rho)*B
    const float C_R1   = 0.02f - 0.5f * 0.1f * 0.1f;       // A - 0.5*b^2
    const float C_P1   = -(0.05f + 0.5f * 0.3f * 0.3f);    // -(alpha + 0.5*theta^2)
    const float TH     = 0.3f;

    // step-0 row
    {
        unsigned base = (unsigned)b * 5u;
        out[base + 0] = x0v; out[base + 1] = r0v; out[base + 2] = pi0;
        out[base + 3] = -p0; out[base + 4] = -dp0;
    }

    float x = x0v, mn = x0v, W = 0.0f, pi = pi0;
    float Rv = r0v, p = p0;

    #pragma unroll 1
    for (int i = 1; i <= NSTEPS; ++i) {
        float dwi = dwp[i - 1];
        x = x + x * C_ADT + pi * C_STDT + pi * SIG * dwi;
        mn = fminf(mn, x);
        W += dwi;
        float t = (float)i * DT;
        Rv = r0v * __expf(C_R1 * t + BEFF * W);
        p  = p0  * __expf(C_P1 * t - TH * W);

        if (i < NSTEPS) {                  // pi not updated at last step
            float s0 = 2.0f * t;           // MULT * t

            ull acc[HID / 2];
            #pragma unroll
            for (int q = 0; q < HID / 2; ++q) acc[q] = sb2p[q];

            #pragma unroll 4
            for (int k = 0; k < HID; ++k) {
                float a1 = fmaf(sW1[k], s0, sb1[k]);
                a1 = fmaf(sW1[HID + k], x,  a1);
                a1 = fmaf(sW1[2 * HID + k], Rv, a1);
                float h = tanh_ap(a1);
                ull hh = pack2(h, h);
                const ulonglong2* wr = (const ulonglong2*)(sW2 + k * HID);
                #pragma unroll
                for (int q = 0; q < HID / 4; ++q) {
                    ulonglong2 w = wr[q];
                    ffma2(acc[2 * q + 0], hh, w.x);
                    ffma2(acc[2 * q + 1], hh, w.y);
                }
            }

            float o0 = sb3s, o1 = 0.0f, o2 = 0.0f, o3 = 0.0f;
            #pragma unroll
            for (int q = 0; q < HID / 2; q += 2) {
                float a0, a1f, a2, a3;
                unpack2(acc[q],     a0, a1f);
                unpack2(acc[q + 1], a2, a3);
                o0 = fmaf(tanh_ap(a0),  sW3[2 * q + 0], o0);
                o1 = fmaf(tanh_ap(a1f), sW3[2 * q + 1], o1);
                o2 = fmaf(tanh_ap(a2),  sW3[2 * q + 2], o2);
                o3 = fmaf(tanh_ap(a3),  sW3[2 * q + 3], o3);
            }
            pi = (o0 + o1) + (o2 + o3);
        }
        unsigned base = ((unsigned)i * BATCH + (unsigned)b) * 5u;
        out[base + 0] = x;  out[base + 1] = Rv; out[base + 2] = pi;
        out[base + 3] = -p; out[base + 4] = -dp0;
    }

    // ---- per-sample loss terms ----
    float xc  = fmaxf(x, 1e-6f);
    float ux  = Rv * rsqrtf(xc);            // R * xc^(gamma-1), gamma=0.5
    float uv  = 2.0f * Rv * sqrtf(xc);      // R * xc^gamma / gamma
    float dpn = fmaxf(1e-6f - mn, 0.0f);
    float pen = 100.0f * dpn * dpn;
    float aa  = p + ux; aa = aa * aa + pen; // (p_fin + ux)^2 + pen
    float bb  = -uv + pen;                  // -u_val + pen

    redA[tid] = aa; redB[tid] = bb;
    __syncthreads();
    for (int s = 64; s > 0; s >>= 1) {
        if (tid < s) { redA[tid] += redA[tid + s]; redB[tid] += redB[tid + s]; }
        __syncthreads();
    }
    if (tid == 0) { g_pA[blockIdx.x] = redA[0]; g_pB[blockIdx.x] = redB[0]; }
}

// ---------------------------------------------------------------------------
// Deterministic final reduction of the 128 block partials -> two losses.
// ---------------------------------------------------------------------------
__global__ void finalize_kernel(float* __restrict__ out)
{
    __shared__ float rA[128], rB[128];
    int tid = threadIdx.x;
    rA[tid] = g_pA[tid]; rB[tid] = g_pB[tid];
    __syncthreads();
    for (int s = 64; s > 0; s >>= 1) {
        if (tid < s) { rA[tid] += rA[tid + s]; rB[tid] += rB[tid + s]; }
        __syncthreads();
    }
    if (tid == 0) {
        float lp  = rA[0] / (float)BATCH;
        float lpi = lp + rB[0] / (float)BATCH;
        unsigned base = (unsigned)(NSTEPS + 1) * BATCH * 5u;
        out[base + 0] = lp;
        out[base + 1] = lpi;
    }
}

extern "C" void kernel_launch(void* const* d_in, const int* in_sizes, int n_in,
                              void* d_out, int out_size)
{
    const float* dw  = (const float*)d_in[0];
    const float* X0  = (const float*)d_in[1];
    const float* R0  = (const float*)d_in[2];
    const float* pW1 = (const float*)d_in[3];  const float* pb1 = (const float*)d_in[4];
    const float* pW2 = (const float*)d_in[5];  const float* pb2 = (const float*)d_in[6];
    const float* pW3 = (const float*)d_in[7];  const float* pb3 = (const float*)d_in[8];
    const float* qW1 = (const float*)d_in[9];  const float* qb1 = (const float*)d_in[10];
    const float* qW2 = (const float*)d_in[11]; const float* qb2 = (const float*)d_in[12];
    const float* qW3 = (const float*)d_in[13]; const float* qb3 = (const float*)d_in[14];
    float* out = (float*)d_out;

    prep_kernel<<<1, 64>>>(X0, R0, pW1, pb1, pW2, pb2, pW3, pb3,
                           qW1, qb1, qW2, qb2, qW3, qb3);
    sim_kernel<<<128, 128>>>(dw, X0, R0, qW1, qb1, qW2, qb2, qW3, qb3, out);
    finalize_kernel<<<1, 128>>>(out);
}